// round 7
// baseline (speedup 1.0000x reference)
#include <cuda_runtime.h>
#include <cuda_bf16.h>
#include <cstdint>
#include <cstddef>

// ---------------- problem constants ----------------
#define TT      64
#define MM      64
#define NROWS   4096      // T*M
#define ROI     2048
#define SPA     4
#define WORD    300
#define ROISPA  2052      // ROI+SPA
#define INW     2352      // ROI+SPA+WORD
#define HH      512
#define DD      256
#define RELIN   556       // D + WORD
#define KP1     2080      // ROISPA padded to 65*32

// ---------------- scratch (device globals; no allocation) ----------------
__device__ __nv_bfloat16 g_Xh[NROWS * KP1], g_Xl[NROWS * KP1];
__device__ __nv_bfloat16 g_W1h_s[HH * KP1], g_W1l_s[HH * KP1];
__device__ __nv_bfloat16 g_W1h_o[HH * KP1], g_W1l_o[HH * KP1];
__device__ __nv_bfloat16 g_Y1h_s[NROWS * HH], g_Y1l_s[NROWS * HH];
__device__ __nv_bfloat16 g_Y1h_o[NROWS * HH], g_Y1l_o[NROWS * HH];
__device__ __nv_bfloat16 g_Y2h_s[NROWS * HH], g_Y2l_s[NROWS * HH];
__device__ __nv_bfloat16 g_Y2h_o[NROWS * HH], g_Y2l_o[NROWS * HH];
__device__ __nv_bfloat16 g_Wfh_s[HH * HH], g_Wfl_s[HH * HH];
__device__ __nv_bfloat16 g_Wfh_o[HH * HH], g_Wfl_o[HH * HH];
__device__ __nv_bfloat16 g_Wcch_s[HH * HH], g_Wccl_s[HH * HH];
__device__ __nv_bfloat16 g_Wcch_o[HH * HH], g_Wccl_o[HH * HH];
__device__ float g_A[NROWS * HH];      // A + bias512 folded in
__device__ float g_B[NROWS * HH];
__device__ float g_Wsum_s[HH * DD], g_Wsum_o[HH * DD];
__device__ float g_Wc_s  [HH * DD], g_Wc_o  [HH * DD];
__device__ float g_c_subj[HH], g_c_obj[HH], g_bias512[HH];
__device__ float g_bf_s[HH], g_bf_o[HH], g_cvec_s[HH], g_cvec_o[HH];
__device__ __nv_bfloat16 g_W2hi[DD * HH];
__device__ __nv_bfloat16 g_W2lo[DD * HH];

// ---------------- helpers ----------------
__device__ __forceinline__ uint32_t smem_u32(const void* p) {
    uint32_t a;
    asm("{ .reg .u64 t; cvta.to.shared.u64 t, %1; cvt.u32.u64 %0, t; }"
        : "=r"(a) : "l"(p));
    return a;
}
__device__ __forceinline__ void ldsm4(uint32_t* r, uint32_t addr) {
    asm volatile("ldmatrix.sync.aligned.m8n8.x4.shared.b16 {%0,%1,%2,%3}, [%4];"
        : "=r"(r[0]), "=r"(r[1]), "=r"(r[2]), "=r"(r[3]) : "r"(addr));
}
__device__ __forceinline__ void mma_bf16(float* c, const uint32_t* a, const uint32_t* b) {
    asm volatile(
        "mma.sync.aligned.m16n8k16.row.col.f32.bf16.bf16.f32 "
        "{%0,%1,%2,%3}, {%4,%5,%6,%7}, {%8,%9}, {%0,%1,%2,%3};"
        : "+f"(c[0]), "+f"(c[1]), "+f"(c[2]), "+f"(c[3])
        : "r"(a[0]), "r"(a[1]), "r"(a[2]), "r"(a[3]), "r"(b[0]), "r"(b[1]));
}
__device__ __forceinline__ void split_bf16(float v, __nv_bfloat16& h, __nv_bfloat16& l) {
    h = __float2bfloat16(v);
    l = __float2bfloat16(v - __bfloat162float(h));
}
__device__ __forceinline__ uint32_t pack_bf(__nv_bfloat16 a, __nv_bfloat16 b) {
    return ((uint32_t)__bfloat16_as_ushort(b) << 16) | __bfloat16_as_ushort(a);
}
// packed split: (v0,v1) -> hp (lo=bf16(v0), hi=bf16(v1)), lp likewise for residuals
__device__ __forceinline__ void split2_bf16(float v0, float v1, uint32_t& hp, uint32_t& lp) {
    asm("cvt.rn.bf16x2.f32 %0, %1, %2;" : "=r"(hp) : "f"(v1), "f"(v0));
    float h0f, h1f;
    asm("{.reg .b16 lo, hi; mov.b32 {lo, hi}, %2; cvt.f32.bf16 %0, lo; cvt.f32.bf16 %1, hi;}"
        : "=f"(h0f), "=f"(h1f) : "r"(hp));
    float l0 = v0 - h0f, l1 = v1 - h1f;
    asm("cvt.rn.bf16x2.f32 %0, %1, %2;" : "=r"(lp) : "f"(l1), "f"(l0));
}
__device__ __forceinline__ void cp16(uint32_t dst, const void* src) {
    asm volatile("cp.async.ca.shared.global [%0], [%1], 16;" :: "r"(dst), "l"(src));
}
__device__ __forceinline__ void cp_commit() {
    asm volatile("cp.async.commit_group;");
}
__device__ __forceinline__ void cp_wait0() {
    asm volatile("cp.async.wait_group 0;" ::: "memory");
}

// ---------------- pack X = [roi | spatial | 0pad] -> bf16 hi/lo ----------------
__global__ void pack_x_kernel(const float* __restrict__ roi,
                              const float* __restrict__ spa) {
    int r = blockIdx.x;
    for (int k = threadIdx.x; k < KP1; k += blockDim.x) {
        float v = 0.f;
        if (k < ROI)         v = roi[(size_t)r * ROI + k];
        else if (k < ROISPA) v = spa[(size_t)r * SPA + (k - ROI)];
        __nv_bfloat16 h, l; split_bf16(v, h, l);
        g_Xh[(size_t)r * KP1 + k] = h;
        g_Xl[(size_t)r * KP1 + k] = l;
    }
}

// ---------------- split layer-1 weights ----------------
__global__ void split_w1_kernel(const float* __restrict__ s_w1,
                                const float* __restrict__ o_w1) {
    int idx = blockIdx.x * 256 + threadIdx.x;
    if (idx >= HH * KP1) return;
    int n = idx / KP1, k = idx - n * KP1;
    float vs = (k < ROISPA) ? s_w1[(size_t)n * INW + k] : 0.f;
    float vo = (k < ROISPA) ? o_w1[(size_t)n * INW + k] : 0.f;
    __nv_bfloat16 h, l;
    split_bf16(vs, h, l); g_W1h_s[idx] = h; g_W1l_s[idx] = l;
    split_bf16(vo, h, l); g_W1h_o[idx] = h; g_W1l_o[idx] = l;
}

// ---------------- split rel_w2 ----------------
__global__ void split_w2_kernel(const float* __restrict__ w2) {
    int idx = blockIdx.x * 256 + threadIdx.x;
    float v = w2[idx];
    __nv_bfloat16 h, l; split_bf16(v, h, l);
    g_W2hi[idx] = h;
    g_W2lo[idx] = l;
}

// ---------------- constant biases + Wsum ----------------
__global__ void pre_vec_kernel(const float* __restrict__ subj_w1, const float* __restrict__ subj_b1,
                               const float* __restrict__ obj_w1,  const float* __restrict__ obj_b1,
                               const float* __restrict__ rel_w1,  const float* __restrict__ rel_b1,
                               const float* __restrict__ subj_emb, const float* __restrict__ obj_emb,
                               const float* __restrict__ pred_emb,
                               const float* __restrict__ fuse_s_w1, const float* __restrict__ fuse_o_w1) {
    int h = blockIdx.x;
    int t = threadIdx.x;
    float s1 = 0.f, s2 = 0.f, s3 = 0.f;
    for (int w = t; w < WORD; w += 128) {
        s1 += subj_w1[(size_t)h * INW + ROISPA + w] * subj_emb[w];
        s2 += obj_w1 [(size_t)h * INW + ROISPA + w] * obj_emb[w];
        s3 += rel_w1 [(size_t)h * RELIN + DD + w]   * pred_emb[w];
    }
    for (int o = 16; o > 0; o >>= 1) {
        s1 += __shfl_down_sync(0xffffffffu, s1, o);
        s2 += __shfl_down_sync(0xffffffffu, s2, o);
        s3 += __shfl_down_sync(0xffffffffu, s3, o);
    }
    __shared__ float red[3][4];
    int wrp = t >> 5, lan = t & 31;
    if (lan == 0) { red[0][wrp] = s1; red[1][wrp] = s2; red[2][wrp] = s3; }
    __syncthreads();
    if (t == 0) {
        g_c_subj[h]  = red[0][0] + red[0][1] + red[0][2] + red[0][3] + subj_b1[h];
        g_c_obj[h]   = red[1][0] + red[1][1] + red[1][2] + red[1][3] + obj_b1[h];
        g_bias512[h] = red[2][0] + red[2][1] + red[2][2] + red[2][3] + rel_b1[h];
    }
    for (int d = t; d < DD; d += 128) {
        g_Wsum_s[h * DD + d] = fuse_s_w1[(size_t)h * (2*DD) + d] + fuse_s_w1[(size_t)h * (2*DD) + DD + d];
        g_Wsum_o[h * DD + d] = fuse_o_w1[(size_t)h * (2*DD) + d] + fuse_o_w1[(size_t)h * (2*DD) + DD + d];
    }
}

// ---------------- tiled NN GEMM: C = A(MxK) @ B(KxN) ----------------
template<bool BF16OUT>
__global__ __launch_bounds__(256)
void nn_gemm_kernel(const float* __restrict__ A0, const float* __restrict__ B0,
                    float* __restrict__ C0, __nv_bfloat16* __restrict__ Ch0, __nv_bfloat16* __restrict__ Cl0,
                    const float* __restrict__ A1, const float* __restrict__ B1,
                    float* __restrict__ C1, __nv_bfloat16* __restrict__ Ch1, __nv_bfloat16* __restrict__ Cl1,
                    int N, int K, int lda, int ldb) {
    __shared__ float Ask[16][68];
    __shared__ float Bs [16][68];
    const int br = blockIdx.z;
    const float* A = br ? A1 : A0;
    const float* B = br ? B1 : B0;
    const int m0 = blockIdx.y * 64, n0 = blockIdx.x * 64;
    const int tid = threadIdx.x;
    const int tr = tid >> 4, tc = tid & 15;
    float acc[4][4];
    #pragma unroll
    for (int i = 0; i < 4; i++)
        #pragma unroll
        for (int j = 0; j < 4; j++) acc[i][j] = 0.f;

    for (int k0 = 0; k0 < K; k0 += 16) {
        {
            int r = tid >> 2, kq = (tid & 3) * 4;
            float4 v = *reinterpret_cast<const float4*>(&A[(size_t)(m0 + r) * lda + k0 + kq]);
            Ask[kq + 0][r] = v.x; Ask[kq + 1][r] = v.y;
            Ask[kq + 2][r] = v.z; Ask[kq + 3][r] = v.w;
        }
        {
            int k = tid >> 4, nq = (tid & 15) * 4;
            float4 v = *reinterpret_cast<const float4*>(&B[(size_t)(k0 + k) * ldb + n0 + nq]);
            *reinterpret_cast<float4*>(&Bs[k][nq]) = v;
        }
        __syncthreads();
        #pragma unroll
        for (int k = 0; k < 16; k++) {
            float a[4], b[4];
            *reinterpret_cast<float4*>(a) = *reinterpret_cast<const float4*>(&Ask[k][tr * 4]);
            *reinterpret_cast<float4*>(b) = *reinterpret_cast<const float4*>(&Bs[k][tc * 4]);
            #pragma unroll
            for (int i = 0; i < 4; i++)
                #pragma unroll
                for (int j = 0; j < 4; j++)
                    acc[i][j] = fmaf(a[i], b[j], acc[i][j]);
        }
        __syncthreads();
    }

    if (BF16OUT) {
        __nv_bfloat16* Ch = br ? Ch1 : Ch0;
        __nv_bfloat16* Cl = br ? Cl1 : Cl0;
        #pragma unroll
        for (int i = 0; i < 4; i++)
            #pragma unroll
            for (int j = 0; j < 4; j++) {
                __nv_bfloat16 h, l; split_bf16(acc[i][j], h, l);
                size_t off = (size_t)(m0 + tr * 4 + i) * N + n0 + tc * 4 + j;
                Ch[off] = h; Cl[off] = l;
            }
    } else {
        float* C = br ? C1 : C0;
        #pragma unroll
        for (int i = 0; i < 4; i++)
            #pragma unroll
            for (int j = 0; j < 4; j++)
                C[(size_t)(m0 + tr * 4 + i) * N + n0 + tc * 4 + j] = acc[i][j];
    }
}

// ---------------- batched small GEMV for bias folds ----------------
// 0: bf_s = Wsum_s@subj_b2 + fuse_s_b1 ; 1: bf_o ;
// 2: cvec_s = Wc_s@fuse_s_b2 + bias512 (fold!) ; 3: cvec_o = Wc_o@fuse_o_b2
__global__ void gemv4_kernel(const float* __restrict__ subj_b2, const float* __restrict__ obj_b2,
                             const float* __restrict__ fuse_s_b1, const float* __restrict__ fuse_o_b1,
                             const float* __restrict__ fuse_s_b2, const float* __restrict__ fuse_o_b2) {
    int which = blockIdx.y;
    const float *A, *v, *add; float* o;
    if      (which == 0) { A = g_Wsum_s; v = subj_b2;  add = fuse_s_b1; o = g_bf_s; }
    else if (which == 1) { A = g_Wsum_o; v = obj_b2;   add = fuse_o_b1; o = g_bf_o; }
    else if (which == 2) { A = g_Wc_s;   v = fuse_s_b2; add = g_bias512; o = g_cvec_s; }
    else                 { A = g_Wc_o;   v = fuse_o_b2; add = nullptr;  o = g_cvec_o; }
    int h = blockIdx.x * 8 + (threadIdx.x >> 5);
    int lane = threadIdx.x & 31;
    float s = 0.f;
    for (int d = lane; d < DD; d += 32) s += A[h * DD + d] * v[d];
    #pragma unroll
    for (int off = 16; off > 0; off >>= 1) s += __shfl_down_sync(0xffffffffu, s, off);
    if (lane == 0) o[h] = s + (add ? add[h] : 0.f);
}

// ================= chain HMMA GEMM (bf16 3-term, cp.async double-buffered) ====
#define CPSTR   80
#define CBUFSZ  40960
#define CSMEM   (512 + 2 * CBUFSZ)   // 82432

template<bool RELU, bool BF16OUT>
__global__ __launch_bounds__(256, 2)
void chain_hmma_kernel(const __nv_bfloat16* __restrict__ Xh0, const __nv_bfloat16* __restrict__ Xl0,
                       const __nv_bfloat16* __restrict__ Xh1, const __nv_bfloat16* __restrict__ Xl1,
                       int ldx,
                       const __nv_bfloat16* __restrict__ Wh0, const __nv_bfloat16* __restrict__ Wl0,
                       const __nv_bfloat16* __restrict__ Wh1, const __nv_bfloat16* __restrict__ Wl1,
                       const float* __restrict__ bias0, const float* __restrict__ bias1,
                       float* __restrict__ C0, float* __restrict__ C1,
                       __nv_bfloat16* __restrict__ Ch0, __nv_bfloat16* __restrict__ Cl0,
                       __nv_bfloat16* __restrict__ Ch1, __nv_bfloat16* __restrict__ Cl1,
                       int N, int K) {
    extern __shared__ char smem[];
    const uint32_t su = smem_u32(smem);
    float* biasS = reinterpret_cast<float*>(smem);

    const int tid  = threadIdx.x;
    const int wid  = tid >> 5;
    const int lane = tid & 31;
    const int wm   = wid >> 1;
    const int wn   = wid & 1;
    const int n0   = blockIdx.x * 128;
    const int m0   = blockIdx.y * 128;
    const int br   = blockIdx.z;

    const __nv_bfloat16* Xh = br ? Xh1 : Xh0;
    const __nv_bfloat16* Xl = br ? Xl1 : Xl0;
    const __nv_bfloat16* Wh = br ? Wh1 : Wh0;
    const __nv_bfloat16* Wl = br ? Wl1 : Wl0;
    const float* bias = br ? bias1 : bias0;

    if (tid < 128) biasS[tid] = bias[n0 + tid];

    auto stage = [&](int k0, int b) {
        uint32_t base = su + 512 + (uint32_t)b * CBUFSZ;
        #pragma unroll
        for (int e = 0; e < 2; e++) {
            int idx = e * 256 + tid;
            int r = idx >> 2, q = idx & 3;
            cp16(base +         r * CPSTR + q * 16, Xh + (size_t)(m0 + r) * ldx + k0 + q * 8);
            cp16(base + 10240 + r * CPSTR + q * 16, Xl + (size_t)(m0 + r) * ldx + k0 + q * 8);
            cp16(base + 20480 + r * CPSTR + q * 16, Wh + (size_t)(n0 + r) * K + k0 + q * 8);
            cp16(base + 30720 + r * CPSTR + q * 16, Wl + (size_t)(n0 + r) * K + k0 + q * 8);
        }
    };

    const uint32_t h_off = (uint32_t)((lane & 15) * CPSTR + (lane >> 4) * 16);
    const uint32_t w_off = (uint32_t)(((lane & 7) + ((lane >> 4) << 3)) * CPSTR
                                      + ((lane >> 3) & 1) * 16);

    float acc[2][8][4];
    #pragma unroll
    for (int mb = 0; mb < 2; mb++)
        #pragma unroll
        for (int nb = 0; nb < 8; nb++)
            #pragma unroll
            for (int q = 0; q < 4; q++) acc[mb][nb][q] = 0.f;

    stage(0, 0); cp_commit();
    const int nk = K / 32;

    for (int c = 0; c < nk; c++) {
        cp_wait0();
        __syncthreads();
        if (c + 1 < nk) { stage((c + 1) * 32, (c + 1) & 1); cp_commit(); }

        const uint32_t base = su + 512 + (uint32_t)(c & 1) * CBUFSZ;
        #pragma unroll
        for (int ks = 0; ks < 2; ks++) {
            #pragma unroll
            for (int term = 0; term < 3; term++) {
                const uint32_t hbase = base + (term == 2 ? 10240 : 0)
                                       + wm * (32 * CPSTR) + ks * 32 + h_off;
                const uint32_t wbase = base + 20480 + (term == 1 ? 10240 : 0)
                                       + wn * (64 * CPSTR) + ks * 32 + w_off;
                uint32_t a[2][4];
                ldsm4(a[0], hbase);
                ldsm4(a[1], hbase + 16 * CPSTR);
                #pragma unroll
                for (int g = 0; g < 4; g++) {
                    uint32_t b[4];
                    ldsm4(b, wbase + g * (16 * CPSTR));
                    mma_bf16(acc[0][g * 2 + 0], a[0], b);
                    mma_bf16(acc[0][g * 2 + 1], a[0], b + 2);
                    mma_bf16(acc[1][g * 2 + 0], a[1], b);
                    mma_bf16(acc[1][g * 2 + 1], a[1], b + 2);
                }
            }
        }
    }

    // ---- epilogue ----
    const int qr = lane >> 2, qc = (lane & 3) * 2;
    float* C = br ? C1 : C0;
    __nv_bfloat16* Ch = br ? Ch1 : Ch0;
    __nv_bfloat16* Cl = br ? Cl1 : Cl0;
    #pragma unroll
    for (int mb = 0; mb < 2; mb++) {
        int rA = m0 + wm * 32 + mb * 16 + qr;
        int rB = rA + 8;
        #pragma unroll
        for (int nb = 0; nb < 8; nb++) {
            int ln = qc + wn * 64 + nb * 8;
            int col = n0 + ln;
            float vA0 = acc[mb][nb][0] + biasS[ln];
            float vA1 = acc[mb][nb][1] + biasS[ln + 1];
            float vB0 = acc[mb][nb][2] + biasS[ln];
            float vB1 = acc[mb][nb][3] + biasS[ln + 1];
            if (RELU) {
                vA0 = fmaxf(vA0, 0.f); vA1 = fmaxf(vA1, 0.f);
                vB0 = fmaxf(vB0, 0.f); vB1 = fmaxf(vB1, 0.f);
            }
            if (BF16OUT) {
                uint32_t hp, lp;
                split2_bf16(vA0, vA1, hp, lp);
                *reinterpret_cast<uint32_t*>(&Ch[(size_t)rA * N + col]) = hp;
                *reinterpret_cast<uint32_t*>(&Cl[(size_t)rA * N + col]) = lp;
                split2_bf16(vB0, vB1, hp, lp);
                *reinterpret_cast<uint32_t*>(&Ch[(size_t)rB * N + col]) = hp;
                *reinterpret_cast<uint32_t*>(&Cl[(size_t)rB * N + col]) = lp;
            } else {
                *reinterpret_cast<float2*>(&C[(size_t)rA * N + col]) = make_float2(vA0, vA1);
                *reinterpret_cast<float2*>(&C[(size_t)rB * N + col]) = make_float2(vB0, vB1);
            }
        }
    }
}

// ================= HMMA pairwise kernel (cp.async double-buffered) =============
// smem layout:
//  0      b2        512
//  512    Hh        10240
//  10752  Hl        10240
//  20992  buf0 { A 2x128B=256 | B 64x144=9216 | Wh 10240 | Wl 10240 } = 29952
//  50944  buf1
#define PW_HH    512
#define PW_HL    10752
#define PW_BUF0  20992
#define PW_BUFSZ 29952
#define PSTR     80
#define PSMEM    (PW_BUF0 + 2 * PW_BUFSZ)   // 80896

__global__ __launch_bounds__(256, 2)
void pairwise_hmma_kernel(const float* __restrict__ b2v,
                          float* __restrict__ out) {
    extern __shared__ char smem[];
    const uint32_t su = smem_u32(smem);
    float* bs2 = reinterpret_cast<float*>(smem);

    const int tid  = threadIdx.x;
    const int wid  = tid >> 5;
    const int lane = tid & 31;
    const int wm   = wid >> 1;
    const int wn   = wid & 1;

    const int n0  = blockIdx.x * 128;
    const int ib2 = blockIdx.y * 2;
    const int t   = blockIdx.z;

    if (tid < 128) bs2[tid] = b2v[n0 + tid];

    const size_t arow0 = (size_t)(t * 64 + ib2) * HH;
    const size_t brow0 = (size_t)(t * 64) * HH;

    auto stage = [&](int k0, int b) {
        uint32_t base = su + PW_BUF0 + (uint32_t)b * PW_BUFSZ;
        if (tid < 16) {                            // A (bias pre-folded): 2 rows x 32 f
            int r = tid >> 3, q = tid & 7;
            cp16(base + r * 128 + q * 16, g_A + arow0 + (size_t)r * HH + k0 + q * 4);
        }
        #pragma unroll
        for (int e = 0; e < 2; e++) {              // B: 64 x 32 f, stride 144B
            int idx = e * 256 + tid;
            int j = idx >> 3, q = idx & 7;
            cp16(base + 256 + j * 144 + q * 16, g_B + brow0 + (size_t)j * HH + k0 + q * 4);
        }
        #pragma unroll
        for (int e = 0; e < 2; e++) {              // Wh/Wl: 128 x 32 bf16
            int idx = e * 256 + tid;
            int n = idx >> 2, q = idx & 3;
            cp16(base + 9472  + n * PSTR + q * 16, g_W2hi + (size_t)(n0 + n) * HH + k0 + q * 8);
            cp16(base + 19712 + n * PSTR + q * 16, g_W2lo + (size_t)(n0 + n) * HH + k0 + q * 8);
        }
    };

    const uint32_t h_off = (uint32_t)((lane & 15) * PSTR + (lane >> 4) * 16);
    const uint32_t w_off = (uint32_t)(((lane & 7) + ((lane >> 4) << 3)) * PSTR
                                      + ((lane >> 3) & 1) * 16);

    float acc[2][8][4];
    #pragma unroll
    for (int mb = 0; mb < 2; mb++)
        #pragma unroll
        for (int nb = 0; nb < 8; nb++)
            #pragma unroll
            for (int q = 0; q < 4; q++) acc[mb][nb][q] = 0.f;

    stage(0, 0); cp_commit();

    for (int c = 0; c < 16; c++) {
        cp_wait0();
        __syncthreads();                 // buf(c) ready; all mma(c-1) reads done
        if (c + 1 < 16) { stage((c + 1) * 32, (c + 1) & 1); cp_commit(); }

        const uint32_t bo = PW_BUF0 + (uint32_t)(c & 1) * PW_BUFSZ;
        const float* AsB = reinterpret_cast<const float*>(smem + bo);
        const float* BsB = reinterpret_cast<const float*>(smem + bo + 256);

        // ---- build Hh/Hl (128 x 32 bf16), bias already folded into A ----
        #pragma unroll
        for (int e = 0; e < 8; e++) {
            int idx = e * 256 + tid;
            int p  = idx >> 4;
            int kp = idx & 15;
            int k  = kp * 2;
            int i  = p >> 6, j = p & 63;
            float2 av = *reinterpret_cast<const float2*>(&AsB[i * 32 + k]);
            float2 bv = *reinterpret_cast<const float2*>(&BsB[j * 36 + k]);
            float v0 = fmaxf(av.x - bv.x, 0.f);
            float v1 = fmaxf(av.y - bv.y, 0.f);
            uint32_t hp, lp;
            split2_bf16(v0, v1, hp, lp);
            *reinterpret_cast<uint32_t*>(smem + PW_HH + p * PSTR + k * 2) = hp;
            *reinterpret_cast<uint32_t*>(smem + PW_HL + p * PSTR + k * 2) = lp;
        }
        __syncthreads();                 // H staged

        const uint32_t base = su + bo;
        #pragma unroll
        for (int ks = 0; ks < 2; ks++) {
            #pragma unroll
            for (int term = 0; term < 3; term++) {
                const uint32_t hbase = su + (term == 2 ? PW_HL : PW_HH)
                                       + wm * (32 * PSTR) + ks * 32 + h_off;
                const uint32_t wbase = base + 9472 + (term == 1 ? 10240 : 0)
                                       + wn * (64 * PSTR) + ks * 32 + w_off;
                uint32_t a[2][4];
                ldsm4(a[0], hbase);
                ldsm4(a[1], hbase + 16 * PSTR);
                #pragma unroll
                for (int g = 0; g < 4; g++) {
                    uint32_t b[4];
                    ldsm4(b, wbase + g * (16 * PSTR));
                    mma_bf16(acc[0][g * 2 + 0], a[0], b);
                    mma_bf16(acc[0][g * 2 + 1], a[0], b + 2);
                    mma_bf16(acc[1][g * 2 + 0], a[1], b);
                    mma_bf16(acc[1][g * 2 + 1], a[1], b + 2);
                }
            }
        }
    }

    const int qr = lane >> 2, qc = (lane & 3) * 2;
    #pragma unroll
    for (int mb = 0; mb < 2; mb++) {
        int rA = wm * 32 + mb * 16 + qr;
        int rB = rA + 8;
        float* oA = out + ((size_t)(t * 64 + ib2 + (rA >> 6)) * 64 + (rA & 63)) * 256
                        + n0 + wn * 64 + qc;
        float* oB = out + ((size_t)(t * 64 + ib2 + (rB >> 6)) * 64 + (rB & 63)) * 256
                        + n0 + wn * 64 + qc;
        #pragma unroll
        for (int nb = 0; nb < 8; nb++) {
            int ln = wn * 64 + nb * 8 + qc;
            float2 vA = make_float2(acc[mb][nb][0] + bs2[ln],
                                    acc[mb][nb][1] + bs2[ln + 1]);
            float2 vB = make_float2(acc[mb][nb][2] + bs2[ln],
                                    acc[mb][nb][3] + bs2[ln + 1]);
            *reinterpret_cast<float2*>(oA + nb * 8) = vA;
            *reinterpret_cast<float2*>(oB + nb * 8) = vB;
        }
    }
}

// ---------------- host launch ----------------
extern "C" void kernel_launch(void* const* d_in, const int* in_sizes, int n_in,
                              void* d_out, int out_size) {
    const float* roi       = (const float*)d_in[0];
    const float* spatial   = (const float*)d_in[1];
    const float* subj_emb  = (const float*)d_in[3];
    const float* obj_emb   = (const float*)d_in[4];
    const float* pred_emb  = (const float*)d_in[5];
    const float* subj_w1   = (const float*)d_in[6];
    const float* subj_b1   = (const float*)d_in[7];
    const float* subj_w2   = (const float*)d_in[8];
    const float* subj_b2   = (const float*)d_in[9];
    const float* obj_w1    = (const float*)d_in[10];
    const float* obj_b1    = (const float*)d_in[11];
    const float* obj_w2    = (const float*)d_in[12];
    const float* obj_b2    = (const float*)d_in[13];
    const float* fuse_s_w1 = (const float*)d_in[14];
    const float* fuse_s_b1 = (const float*)d_in[15];
    const float* fuse_s_w2 = (const float*)d_in[16];
    const float* fuse_s_b2 = (const float*)d_in[17];
    const float* fuse_o_w1 = (const float*)d_in[18];
    const float* fuse_o_b1 = (const float*)d_in[19];
    const float* fuse_o_w2 = (const float*)d_in[20];
    const float* fuse_o_b2 = (const float*)d_in[21];
    const float* W_rs      = (const float*)d_in[22];
    const float* W_ro      = (const float*)d_in[23];
    const float* rel_w1    = (const float*)d_in[24];
    const float* rel_b1    = (const float*)d_in[25];
    const float* rel_w2    = (const float*)d_in[26];
    const float* rel_b2    = (const float*)d_in[27];
    float* out = (float*)d_out;

    __nv_bfloat16 *pXh, *pXl;
    __nv_bfloat16 *pW1h_s, *pW1l_s, *pW1h_o, *pW1l_o;
    __nv_bfloat16 *pY1h_s, *pY1l_s, *pY1h_o, *pY1l_o;
    __nv_bfloat16 *pY2h_s, *pY2l_s, *pY2h_o, *pY2l_o;
    __nv_bfloat16 *pWfh_s, *pWfl_s, *pWfh_o, *pWfl_o;
    __nv_bfloat16 *pWcch_s, *pWccl_s, *pWcch_o, *pWccl_o;
    float *pA, *pB, *pWsum_s, *pWsum_o, *pWc_s, *pWc_o;
    float *pc_subj, *pc_obj, *pbf_s, *pbf_o, *pcv_s, *pcv_o;
    cudaGetSymbolAddress((void**)&pXh, g_Xh);
    cudaGetSymbolAddress((void**)&pXl, g_Xl);
    cudaGetSymbolAddress((void**)&pW1h_s, g_W1h_s);
    cudaGetSymbolAddress((void**)&pW1l_s, g_W1l_s);
    cudaGetSymbolAddress((void**)&pW1h_o, g_W1h_o);
    cudaGetSymbolAddress((void**)&pW1l_o, g_W1l_o);
    cudaGetSymbolAddress((void**)&pY1h_s, g_Y1h_s);
    cudaGetSymbolAddress((void**)&pY1l_s, g_Y1l_s);
    cudaGetSymbolAddress((void**)&pY1h_o, g_Y1h_o);
    cudaGetSymbolAddress((void**)&pY1l_o, g_Y1l_o);
    cudaGetSymbolAddress((void**)&pY2h_s, g_Y2h_s);
    cudaGetSymbolAddress((void**)&pY2l_s, g_Y2l_s);
    cudaGetSymbolAddress((void**)&pY2h_o, g_Y2h_o);
    cudaGetSymbolAddress((void**)&pY2l_o, g_Y2l_o);
    cudaGetSymbolAddress((void**)&pWfh_s, g_Wfh_s);
    cudaGetSymbolAddress((void**)&pWfl_s, g_Wfl_s);
    cudaGetSymbolAddress((void**)&pWfh_o, g_Wfh_o);
    cudaGetSymbolAddress((void**)&pWfl_o, g_Wfl_o);
    cudaGetSymbolAddress((void**)&pWcch_s, g_Wcch_s);
    cudaGetSymbolAddress((void**)&pWccl_s, g_Wccl_s);
    cudaGetSymbolAddress((void**)&pWcch_o, g_Wcch_o);
    cudaGetSymbolAddress((void**)&pWccl_o, g_Wccl_o);
    cudaGetSymbolAddress((void**)&pA, g_A);
    cudaGetSymbolAddress((void**)&pB, g_B);
    cudaGetSymbolAddress((void**)&pWsum_s, g_Wsum_s);
    cudaGetSymbolAddress((void**)&pWsum_o, g_Wsum_o);
    cudaGetSymbolAddress((void**)&pWc_s, g_Wc_s);
    cudaGetSymbolAddress((void**)&pWc_o, g_Wc_o);
    cudaGetSymbolAddress((void**)&pc_subj, g_c_subj);
    cudaGetSymbolAddress((void**)&pc_obj,  g_c_obj);
    cudaGetSymbolAddress((void**)&pbf_s,  g_bf_s);
    cudaGetSymbolAddress((void**)&pbf_o,  g_bf_o);
    cudaGetSymbolAddress((void**)&pcv_s,  g_cvec_s);
    cudaGetSymbolAddress((void**)&pcv_o,  g_cvec_o);

    static bool attr_set = false;
    if (!attr_set) {
        cudaFuncSetAttribute(pairwise_hmma_kernel,
                             cudaFuncAttributeMaxDynamicSharedMemorySize, PSMEM);
        cudaFuncSetAttribute(chain_hmma_kernel<true, true>,
                             cudaFuncAttributeMaxDynamicSharedMemorySize, CSMEM);
        cudaFuncSetAttribute(chain_hmma_kernel<false, false>,
                             cudaFuncAttributeMaxDynamicSharedMemorySize, CSMEM);
        attr_set = true;
    }

    // 1. pack + precompute
    pack_x_kernel<<<NROWS, 256>>>(roi, spatial);
    split_w1_kernel<<<(HH * KP1 + 255) / 256, 256>>>(subj_w1, obj_w1);
    split_w2_kernel<<<512, 256>>>(rel_w2);
    pre_vec_kernel<<<HH, 128>>>(subj_w1, subj_b1, obj_w1, obj_b1, rel_w1, rel_b1,
                                subj_emb, obj_emb, pred_emb, fuse_s_w1, fuse_o_w1);
    nn_gemm_kernel<false><<<dim3(4, 8, 2), 256>>>(
        rel_w1, W_rs, pWc_s, nullptr, nullptr,
        rel_w1, W_ro, pWc_o, nullptr, nullptr,
        DD, DD, RELIN, DD);
    nn_gemm_kernel<true><<<dim3(8, 8, 2), 256>>>(
        pWsum_s, subj_w2, nullptr, pWfh_s, pWfl_s,
        pWsum_o, obj_w2,  nullptr, pWfh_o, pWfl_o,
        HH, DD, DD, HH);
    nn_gemm_kernel<true><<<dim3(8, 8, 2), 256>>>(
        pWc_s, fuse_s_w2, nullptr, pWcch_s, pWccl_s,
        pWc_o, fuse_o_w2, nullptr, pWcch_o, pWccl_o,
        HH, DD, DD, HH);
    gemv4_kernel<<<dim3(64, 4), 256>>>(subj_b2, obj_b2, fuse_s_b1, fuse_o_b1,
                                       fuse_s_b2, fuse_o_b2);

    dim3 cgrid(HH / 128, NROWS / 128, 2);

    // 2. layer 1: relu(X @ W1^T + c) -> Y1 hi/lo
    chain_hmma_kernel<true, true><<<cgrid, 256, CSMEM>>>(
        pXh, pXl, pXh, pXl, KP1,
        pW1h_s, pW1l_s, pW1h_o, pW1l_o,
        pc_subj, pc_obj,
        nullptr, nullptr,
        pY1h_s, pY1l_s, pY1h_o, pY1l_o,
        HH, KP1);

    // 3. layer 2: relu(Y1 @ Wf^T + bf) -> Y2 hi/lo
    chain_hmma_kernel<true, true><<<cgrid, 256, CSMEM>>>(
        pY1h_s, pY1l_s, pY1h_o, pY1l_o, HH,
        pWfh_s, pWfl_s, pWfh_o, pWfl_o,
        pbf_s, pbf_o,
        nullptr, nullptr,
        pY2h_s, pY2l_s, pY2h_o, pY2l_o,
        HH, HH);

    // 4. layer 3: Y2 @ Wcc^T + cvec(+bias512 for A) -> A/B fp32
    chain_hmma_kernel<false, false><<<cgrid, 256, CSMEM>>>(
        pY2h_s, pY2l_s, pY2h_o, pY2l_o, HH,
        pWcch_s, pWccl_s, pWcch_o, pWccl_o,
        pcv_s, pcv_o,
        pA, pB,
        nullptr, nullptr, nullptr, nullptr,
        HH, HH);

    // 5. pairwise GEMM (HMMA, pipelined)
    pairwise_hmma_kernel<<<dim3(2, 32, 64), 256, PSMEM>>>(rel_b2, out);

    (void)in_sizes; (void)n_in; (void)out_size;
}

// round 8
// speedup vs baseline: 1.2564x; 1.2564x over previous
#include <cuda_runtime.h>
#include <cuda_bf16.h>
#include <cuda_fp16.h>
#include <cstdint>
#include <cstddef>

// ---------------- problem constants ----------------
#define TT      64
#define MM      64
#define NROWS   4096      // T*M
#define ROI     2048
#define SPA     4
#define WORD    300
#define ROISPA  2052      // ROI+SPA
#define INW     2352      // ROI+SPA+WORD
#define HH      512
#define DD      256
#define RELIN   556       // D + WORD
#define KP1     2080      // ROISPA padded to 65*32

// ---------------- scratch (device globals; no allocation) ----------------
__device__ __half g_X16 [NROWS * KP1];                      // activations, single fp16 plane
__device__ __half g_W1h_s[HH * KP1], g_W1l_s[HH * KP1];     // weights split hi/lo fp16
__device__ __half g_W1h_o[HH * KP1], g_W1l_o[HH * KP1];
__device__ __half g_Y1_s[NROWS * HH], g_Y1_o[NROWS * HH];
__device__ __half g_Y2_s[NROWS * HH], g_Y2_o[NROWS * HH];
__device__ __half g_Wfh_s[HH * HH], g_Wfl_s[HH * HH];
__device__ __half g_Wfh_o[HH * HH], g_Wfl_o[HH * HH];
__device__ __half g_Wcch_s[HH * HH], g_Wccl_s[HH * HH];
__device__ __half g_Wcch_o[HH * HH], g_Wccl_o[HH * HH];
__device__ float g_A[NROWS * HH];      // A + bias512 folded in
__device__ float g_B[NROWS * HH];
__device__ float g_Wsum_s[HH * DD], g_Wsum_o[HH * DD];
__device__ float g_Wc_s  [HH * DD], g_Wc_o  [HH * DD];
__device__ float g_c_subj[HH], g_c_obj[HH], g_bias512[HH];
__device__ float g_bf_s[HH], g_bf_o[HH], g_cvec_s[HH], g_cvec_o[HH];
__device__ __half g_W2h[DD * HH];
__device__ __half g_W2l[DD * HH];

// ---------------- helpers ----------------
__device__ __forceinline__ uint32_t smem_u32(const void* p) {
    uint32_t a;
    asm("{ .reg .u64 t; cvta.to.shared.u64 t, %1; cvt.u32.u64 %0, t; }"
        : "=r"(a) : "l"(p));
    return a;
}
__device__ __forceinline__ void ldsm4(uint32_t* r, uint32_t addr) {
    asm volatile("ldmatrix.sync.aligned.m8n8.x4.shared.b16 {%0,%1,%2,%3}, [%4];"
        : "=r"(r[0]), "=r"(r[1]), "=r"(r[2]), "=r"(r[3]) : "r"(addr));
}
__device__ __forceinline__ void mma_f16(float* c, const uint32_t* a, const uint32_t* b) {
    asm volatile(
        "mma.sync.aligned.m16n8k16.row.col.f32.f16.f16.f32 "
        "{%0,%1,%2,%3}, {%4,%5,%6,%7}, {%8,%9}, {%0,%1,%2,%3};"
        : "+f"(c[0]), "+f"(c[1]), "+f"(c[2]), "+f"(c[3])
        : "r"(a[0]), "r"(a[1]), "r"(a[2]), "r"(a[3]), "r"(b[0]), "r"(b[1]));
}
__device__ __forceinline__ void split_f16(float v, __half& h, __half& l) {
    h = __float2half_rn(v);
    l = __float2half_rn(v - __half2float(h));
}
__device__ __forceinline__ void cp16(uint32_t dst, const void* src) {
    asm volatile("cp.async.ca.shared.global [%0], [%1], 16;" :: "r"(dst), "l"(src));
}
__device__ __forceinline__ void cp_commit() {
    asm volatile("cp.async.commit_group;");
}
__device__ __forceinline__ void cp_wait0() {
    asm volatile("cp.async.wait_group 0;" ::: "memory");
}

// ---------------- pack X = [roi | spatial | 0pad] -> fp16 ----------------
__global__ void pack_x_kernel(const float* __restrict__ roi,
                              const float* __restrict__ spa) {
    int r = blockIdx.x;
    for (int k = threadIdx.x; k < KP1; k += blockDim.x) {
        float v = 0.f;
        if (k < ROI)         v = roi[(size_t)r * ROI + k];
        else if (k < ROISPA) v = spa[(size_t)r * SPA + (k - ROI)];
        g_X16[(size_t)r * KP1 + k] = __float2half_rn(v);
    }
}

// ---------------- split layer-1 weights -> fp16 hi/lo ----------------
__global__ void split_w1_kernel(const float* __restrict__ s_w1,
                                const float* __restrict__ o_w1) {
    int idx = blockIdx.x * 256 + threadIdx.x;
    if (idx >= HH * KP1) return;
    int n = idx / KP1, k = idx - n * KP1;
    float vs = (k < ROISPA) ? s_w1[(size_t)n * INW + k] : 0.f;
    float vo = (k < ROISPA) ? o_w1[(size_t)n * INW + k] : 0.f;
    __half h, l;
    split_f16(vs, h, l); g_W1h_s[idx] = h; g_W1l_s[idx] = l;
    split_f16(vo, h, l); g_W1h_o[idx] = h; g_W1l_o[idx] = l;
}

// ---------------- split rel_w2 -> fp16 hi/lo ----------------
__global__ void split_w2_kernel(const float* __restrict__ w2) {
    int idx = blockIdx.x * 256 + threadIdx.x;
    float v = w2[idx];
    __half h, l; split_f16(v, h, l);
    g_W2h[idx] = h;
    g_W2l[idx] = l;
}

// ---------------- constant biases + Wsum ----------------
__global__ void pre_vec_kernel(const float* __restrict__ subj_w1, const float* __restrict__ subj_b1,
                               const float* __restrict__ obj_w1,  const float* __restrict__ obj_b1,
                               const float* __restrict__ rel_w1,  const float* __restrict__ rel_b1,
                               const float* __restrict__ subj_emb, const float* __restrict__ obj_emb,
                               const float* __restrict__ pred_emb,
                               const float* __restrict__ fuse_s_w1, const float* __restrict__ fuse_o_w1) {
    int h = blockIdx.x;
    int t = threadIdx.x;
    float s1 = 0.f, s2 = 0.f, s3 = 0.f;
    for (int w = t; w < WORD; w += 128) {
        s1 += subj_w1[(size_t)h * INW + ROISPA + w] * subj_emb[w];
        s2 += obj_w1 [(size_t)h * INW + ROISPA + w] * obj_emb[w];
        s3 += rel_w1 [(size_t)h * RELIN + DD + w]   * pred_emb[w];
    }
    for (int o = 16; o > 0; o >>= 1) {
        s1 += __shfl_down_sync(0xffffffffu, s1, o);
        s2 += __shfl_down_sync(0xffffffffu, s2, o);
        s3 += __shfl_down_sync(0xffffffffu, s3, o);
    }
    __shared__ float red[3][4];
    int wrp = t >> 5, lan = t & 31;
    if (lan == 0) { red[0][wrp] = s1; red[1][wrp] = s2; red[2][wrp] = s3; }
    __syncthreads();
    if (t == 0) {
        g_c_subj[h]  = red[0][0] + red[0][1] + red[0][2] + red[0][3] + subj_b1[h];
        g_c_obj[h]   = red[1][0] + red[1][1] + red[1][2] + red[1][3] + obj_b1[h];
        g_bias512[h] = red[2][0] + red[2][1] + red[2][2] + red[2][3] + rel_b1[h];
    }
    for (int d = t; d < DD; d += 128) {
        g_Wsum_s[h * DD + d] = fuse_s_w1[(size_t)h * (2*DD) + d] + fuse_s_w1[(size_t)h * (2*DD) + DD + d];
        g_Wsum_o[h * DD + d] = fuse_o_w1[(size_t)h * (2*DD) + d] + fuse_o_w1[(size_t)h * (2*DD) + DD + d];
    }
}

// ---------------- tiled NN GEMM: C = A(MxK) @ B(KxN) ----------------
template<bool F16OUT>
__global__ __launch_bounds__(256)
void nn_gemm_kernel(const float* __restrict__ A0, const float* __restrict__ B0,
                    float* __restrict__ C0, __half* __restrict__ Ch0, __half* __restrict__ Cl0,
                    const float* __restrict__ A1, const float* __restrict__ B1,
                    float* __restrict__ C1, __half* __restrict__ Ch1, __half* __restrict__ Cl1,
                    int N, int K, int lda, int ldb) {
    __shared__ float Ask[16][68];
    __shared__ float Bs [16][68];
    const int br = blockIdx.z;
    const float* A = br ? A1 : A0;
    const float* B = br ? B1 : B0;
    const int m0 = blockIdx.y * 64, n0 = blockIdx.x * 64;
    const int tid = threadIdx.x;
    const int tr = tid >> 4, tc = tid & 15;
    float acc[4][4];
    #pragma unroll
    for (int i = 0; i < 4; i++)
        #pragma unroll
        for (int j = 0; j < 4; j++) acc[i][j] = 0.f;

    for (int k0 = 0; k0 < K; k0 += 16) {
        {
            int r = tid >> 2, kq = (tid & 3) * 4;
            float4 v = *reinterpret_cast<const float4*>(&A[(size_t)(m0 + r) * lda + k0 + kq]);
            Ask[kq + 0][r] = v.x; Ask[kq + 1][r] = v.y;
            Ask[kq + 2][r] = v.z; Ask[kq + 3][r] = v.w;
        }
        {
            int k = tid >> 4, nq = (tid & 15) * 4;
            float4 v = *reinterpret_cast<const float4*>(&B[(size_t)(k0 + k) * ldb + n0 + nq]);
            *reinterpret_cast<float4*>(&Bs[k][nq]) = v;
        }
        __syncthreads();
        #pragma unroll
        for (int k = 0; k < 16; k++) {
            float a[4], b[4];
            *reinterpret_cast<float4*>(a) = *reinterpret_cast<const float4*>(&Ask[k][tr * 4]);
            *reinterpret_cast<float4*>(b) = *reinterpret_cast<const float4*>(&Bs[k][tc * 4]);
            #pragma unroll
            for (int i = 0; i < 4; i++)
                #pragma unroll
                for (int j = 0; j < 4; j++)
                    acc[i][j] = fmaf(a[i], b[j], acc[i][j]);
        }
        __syncthreads();
    }

    if (F16OUT) {
        __half* Ch = br ? Ch1 : Ch0;
        __half* Cl = br ? Cl1 : Cl0;
        #pragma unroll
        for (int i = 0; i < 4; i++)
            #pragma unroll
            for (int j = 0; j < 4; j++) {
                __half h, l; split_f16(acc[i][j], h, l);
                size_t off = (size_t)(m0 + tr * 4 + i) * N + n0 + tc * 4 + j;
                Ch[off] = h; Cl[off] = l;
            }
    } else {
        float* C = br ? C1 : C0;
        #pragma unroll
        for (int i = 0; i < 4; i++)
            #pragma unroll
            for (int j = 0; j < 4; j++)
                C[(size_t)(m0 + tr * 4 + i) * N + n0 + tc * 4 + j] = acc[i][j];
    }
}

// ---------------- batched small GEMV for bias folds ----------------
__global__ void gemv4_kernel(const float* __restrict__ subj_b2, const float* __restrict__ obj_b2,
                             const float* __restrict__ fuse_s_b1, const float* __restrict__ fuse_o_b1,
                             const float* __restrict__ fuse_s_b2, const float* __restrict__ fuse_o_b2) {
    int which = blockIdx.y;
    const float *A, *v, *add; float* o;
    if      (which == 0) { A = g_Wsum_s; v = subj_b2;  add = fuse_s_b1; o = g_bf_s; }
    else if (which == 1) { A = g_Wsum_o; v = obj_b2;   add = fuse_o_b1; o = g_bf_o; }
    else if (which == 2) { A = g_Wc_s;   v = fuse_s_b2; add = g_bias512; o = g_cvec_s; }
    else                 { A = g_Wc_o;   v = fuse_o_b2; add = nullptr;  o = g_cvec_o; }
    int h = blockIdx.x * 8 + (threadIdx.x >> 5);
    int lane = threadIdx.x & 31;
    float s = 0.f;
    for (int d = lane; d < DD; d += 32) s += A[h * DD + d] * v[d];
    #pragma unroll
    for (int off = 16; off > 0; off >>= 1) s += __shfl_down_sync(0xffffffffu, s, off);
    if (lane == 0) o[h] = s + (add ? add[h] : 0.f);
}

// ================= chain HMMA GEMM (fp16 2-term, cp.async double-buffered) ====
// planes per buffer: X (10240) | Wh (10240) | Wl (10240)
#define CPSTR   80
#define CBUFSZ  30720
#define CSMEM   (512 + 2 * CBUFSZ)   // 61952

template<bool RELU, bool F16OUT>
__global__ __launch_bounds__(256, 2)
void chain_hmma_kernel(const __half* __restrict__ X0, const __half* __restrict__ X1,
                       int ldx,
                       const __half* __restrict__ Wh0, const __half* __restrict__ Wl0,
                       const __half* __restrict__ Wh1, const __half* __restrict__ Wl1,
                       const float* __restrict__ bias0, const float* __restrict__ bias1,
                       float* __restrict__ C0, float* __restrict__ C1,
                       __half* __restrict__ Co0, __half* __restrict__ Co1,
                       int N, int K) {
    extern __shared__ char smem[];
    const uint32_t su = smem_u32(smem);
    float* biasS = reinterpret_cast<float*>(smem);

    const int tid  = threadIdx.x;
    const int wid  = tid >> 5;
    const int lane = tid & 31;
    const int wm   = wid >> 1;
    const int wn   = wid & 1;
    const int n0   = blockIdx.x * 128;
    const int m0   = blockIdx.y * 128;
    const int br   = blockIdx.z;

    const __half* X  = br ? X1 : X0;
    const __half* Wh = br ? Wh1 : Wh0;
    const __half* Wl = br ? Wl1 : Wl0;
    const float* bias = br ? bias1 : bias0;

    if (tid < 128) biasS[tid] = bias[n0 + tid];

    auto stage = [&](int k0, int b) {
        uint32_t base = su + 512 + (uint32_t)b * CBUFSZ;
        #pragma unroll
        for (int e = 0; e < 2; e++) {
            int idx = e * 256 + tid;
            int r = idx >> 2, q = idx & 3;
            cp16(base +         r * CPSTR + q * 16, X  + (size_t)(m0 + r) * ldx + k0 + q * 8);
            cp16(base + 10240 + r * CPSTR + q * 16, Wh + (size_t)(n0 + r) * K + k0 + q * 8);
            cp16(base + 20480 + r * CPSTR + q * 16, Wl + (size_t)(n0 + r) * K + k0 + q * 8);
        }
    };

    const uint32_t h_off = (uint32_t)((lane & 15) * CPSTR + (lane >> 4) * 16);
    const uint32_t w_off = (uint32_t)(((lane & 7) + ((lane >> 4) << 3)) * CPSTR
                                      + ((lane >> 3) & 1) * 16);

    float acc[2][8][4];
    #pragma unroll
    for (int mb = 0; mb < 2; mb++)
        #pragma unroll
        for (int nb = 0; nb < 8; nb++)
            #pragma unroll
            for (int q = 0; q < 4; q++) acc[mb][nb][q] = 0.f;

    stage(0, 0); cp_commit();
    const int nk = K / 32;

    for (int c = 0; c < nk; c++) {
        cp_wait0();
        __syncthreads();
        if (c + 1 < nk) { stage((c + 1) * 32, (c + 1) & 1); cp_commit(); }

        const uint32_t base = su + 512 + (uint32_t)(c & 1) * CBUFSZ;
        #pragma unroll
        for (int ks = 0; ks < 2; ks++) {
            uint32_t a[2][4];
            const uint32_t hbase = base + wm * (32 * CPSTR) + ks * 32 + h_off;
            ldsm4(a[0], hbase);
            ldsm4(a[1], hbase + 16 * CPSTR);
            #pragma unroll
            for (int term = 0; term < 2; term++) {
                const uint32_t wbase = base + 10240 + term * 10240
                                       + wn * (64 * CPSTR) + ks * 32 + w_off;
                #pragma unroll
                for (int g = 0; g < 4; g++) {
                    uint32_t b[4];
                    ldsm4(b, wbase + g * (16 * CPSTR));
                    mma_f16(acc[0][g * 2 + 0], a[0], b);
                    mma_f16(acc[0][g * 2 + 1], a[0], b + 2);
                    mma_f16(acc[1][g * 2 + 0], a[1], b);
                    mma_f16(acc[1][g * 2 + 1], a[1], b + 2);
                }
            }
        }
    }

    // ---- epilogue ----
    const int qr = lane >> 2, qc = (lane & 3) * 2;
    float* C = br ? C1 : C0;
    __half* Co = br ? Co1 : Co0;
    #pragma unroll
    for (int mb = 0; mb < 2; mb++) {
        int rA = m0 + wm * 32 + mb * 16 + qr;
        int rB = rA + 8;
        #pragma unroll
        for (int nb = 0; nb < 8; nb++) {
            int ln = qc + wn * 64 + nb * 8;
            int col = n0 + ln;
            float vA0 = acc[mb][nb][0] + biasS[ln];
            float vA1 = acc[mb][nb][1] + biasS[ln + 1];
            float vB0 = acc[mb][nb][2] + biasS[ln];
            float vB1 = acc[mb][nb][3] + biasS[ln + 1];
            if (RELU) {
                vA0 = fmaxf(vA0, 0.f); vA1 = fmaxf(vA1, 0.f);
                vB0 = fmaxf(vB0, 0.f); vB1 = fmaxf(vB1, 0.f);
            }
            if (F16OUT) {
                *reinterpret_cast<__half2*>(&Co[(size_t)rA * N + col]) = __floats2half2_rn(vA0, vA1);
                *reinterpret_cast<__half2*>(&Co[(size_t)rB * N + col]) = __floats2half2_rn(vB0, vB1);
            } else {
                *reinterpret_cast<float2*>(&C[(size_t)rA * N + col]) = make_float2(vA0, vA1);
                *reinterpret_cast<float2*>(&C[(size_t)rB * N + col]) = make_float2(vB0, vB1);
            }
        }
    }
}

// ================= HMMA pairwise kernel (fp16 2-term, cp.async pipelined) ======
// smem layout:
//  0      b2        512
//  512    H (fp16)  10240
//  10752  buf0 { A 2x128B=256 | B 64x144=9216 | Wh 10240 | Wl 10240 } = 29952
//  40704  buf1
#define PW_H     512
#define PW_BUF0  10752
#define PW_BUFSZ 29952
#define PSTR     80
#define PSMEM    (PW_BUF0 + 2 * PW_BUFSZ)   // 70656

__global__ __launch_bounds__(256, 2)
void pairwise_hmma_kernel(const float* __restrict__ b2v,
                          float* __restrict__ out) {
    extern __shared__ char smem[];
    const uint32_t su = smem_u32(smem);
    float* bs2 = reinterpret_cast<float*>(smem);

    const int tid  = threadIdx.x;
    const int wid  = tid >> 5;
    const int lane = tid & 31;
    const int wm   = wid >> 1;
    const int wn   = wid & 1;

    const int n0  = blockIdx.x * 128;
    const int ib2 = blockIdx.y * 2;
    const int t   = blockIdx.z;

    if (tid < 128) bs2[tid] = b2v[n0 + tid];

    const size_t arow0 = (size_t)(t * 64 + ib2) * HH;
    const size_t brow0 = (size_t)(t * 64) * HH;

    auto stage = [&](int k0, int b) {
        uint32_t base = su + PW_BUF0 + (uint32_t)b * PW_BUFSZ;
        if (tid < 16) {                            // A (bias pre-folded): 2 rows x 32 f
            int r = tid >> 3, q = tid & 7;
            cp16(base + r * 128 + q * 16, g_A + arow0 + (size_t)r * HH + k0 + q * 4);
        }
        #pragma unroll
        for (int e = 0; e < 2; e++) {              // B: 64 x 32 f, stride 144B
            int idx = e * 256 + tid;
            int j = idx >> 3, q = idx & 7;
            cp16(base + 256 + j * 144 + q * 16, g_B + brow0 + (size_t)j * HH + k0 + q * 4);
        }
        #pragma unroll
        for (int e = 0; e < 2; e++) {              // Wh/Wl: 128 x 32 fp16
            int idx = e * 256 + tid;
            int n = idx >> 2, q = idx & 3;
            cp16(base + 9472  + n * PSTR + q * 16, g_W2h + (size_t)(n0 + n) * HH + k0 + q * 8);
            cp16(base + 19712 + n * PSTR + q * 16, g_W2l + (size_t)(n0 + n) * HH + k0 + q * 8);
        }
    };

    const uint32_t h_off = (uint32_t)((lane & 15) * PSTR + (lane >> 4) * 16);
    const uint32_t w_off = (uint32_t)(((lane & 7) + ((lane >> 4) << 3)) * PSTR
                                      + ((lane >> 3) & 1) * 16);

    float acc[2][8][4];
    #pragma unroll
    for (int mb = 0; mb < 2; mb++)
        #pragma unroll
        for (int nb = 0; nb < 8; nb++)
            #pragma unroll
            for (int q = 0; q < 4; q++) acc[mb][nb][q] = 0.f;

    stage(0, 0); cp_commit();

    for (int c = 0; c < 16; c++) {
        cp_wait0();
        __syncthreads();                 // buf(c) ready; all mma(c-1) reads done
        if (c + 1 < 16) { stage((c + 1) * 32, (c + 1) & 1); cp_commit(); }

        const uint32_t bo = PW_BUF0 + (uint32_t)(c & 1) * PW_BUFSZ;
        const float* AsB = reinterpret_cast<const float*>(smem + bo);
        const float* BsB = reinterpret_cast<const float*>(smem + bo + 256);

        // ---- build H (128 x 32 fp16), bias pre-folded into A ----
        #pragma unroll
        for (int e = 0; e < 8; e++) {
            int idx = e * 256 + tid;
            int p  = idx >> 4;
            int kp = idx & 15;
            int k  = kp * 2;
            int i  = p >> 6, j = p & 63;
            float2 av = *reinterpret_cast<const float2*>(&AsB[i * 32 + k]);
            float2 bv = *reinterpret_cast<const float2*>(&BsB[j * 36 + k]);
            float v0 = fmaxf(av.x - bv.x, 0.f);
            float v1 = fmaxf(av.y - bv.y, 0.f);
            *reinterpret_cast<__half2*>(smem + PW_H + p * PSTR + k * 2) =
                __floats2half2_rn(v0, v1);
        }
        __syncthreads();                 // H staged

        const uint32_t base = su + bo;
        #pragma unroll
        for (int ks = 0; ks < 2; ks++) {
            uint32_t a[2][4];
            const uint32_t hbase = su + PW_H + wm * (32 * PSTR) + ks * 32 + h_off;
            ldsm4(a[0], hbase);
            ldsm4(a[1], hbase + 16 * PSTR);
            #pragma unroll
            for (int term = 0; term < 2; term++) {
                const uint32_t wbase = base + 9472 + term * 10240
                                       + wn * (64 * PSTR) + ks * 32 + w_off;
                #pragma unroll
                for (int g = 0; g < 4; g++) {
                    uint32_t b[4];
                    ldsm4(b, wbase + g * (16 * PSTR));
                    mma_f16(acc[0][g * 2 + 0], a[0], b);
                    mma_f16(acc[0][g * 2 + 1], a[0], b + 2);
                    mma_f16(acc[1][g * 2 + 0], a[1], b);
                    mma_f16(acc[1][g * 2 + 1], a[1], b + 2);
                }
            }
        }
    }

    const int qr = lane >> 2, qc = (lane & 3) * 2;
    #pragma unroll
    for (int mb = 0; mb < 2; mb++) {
        int rA = wm * 32 + mb * 16 + qr;
        int rB = rA + 8;
        float* oA = out + ((size_t)(t * 64 + ib2 + (rA >> 6)) * 64 + (rA & 63)) * 256
                        + n0 + wn * 64 + qc;
        float* oB = out + ((size_t)(t * 64 + ib2 + (rB >> 6)) * 64 + (rB & 63)) * 256
                        + n0 + wn * 64 + qc;
        #pragma unroll
        for (int nb = 0; nb < 8; nb++) {
            int ln = wn * 64 + nb * 8 + qc;
            float2 vA = make_float2(acc[mb][nb][0] + bs2[ln],
                                    acc[mb][nb][1] + bs2[ln + 1]);
            float2 vB = make_float2(acc[mb][nb][2] + bs2[ln],
                                    acc[mb][nb][3] + bs2[ln + 1]);
            *reinterpret_cast<float2*>(oA + nb * 8) = vA;
            *reinterpret_cast<float2*>(oB + nb * 8) = vB;
        }
    }
}

// ---------------- host launch ----------------
extern "C" void kernel_launch(void* const* d_in, const int* in_sizes, int n_in,
                              void* d_out, int out_size) {
    const float* roi       = (const float*)d_in[0];
    const float* spatial   = (const float*)d_in[1];
    const float* subj_emb  = (const float*)d_in[3];
    const float* obj_emb   = (const float*)d_in[4];
    const float* pred_emb  = (const float*)d_in[5];
    const float* subj_w1   = (const float*)d_in[6];
    const float* subj_b1   = (const float*)d_in[7];
    const float* subj_w2   = (const float*)d_in[8];
    const float* subj_b2   = (const float*)d_in[9];
    const float* obj_w1    = (const float*)d_in[10];
    const float* obj_b1    = (const float*)d_in[11];
    const float* obj_w2    = (const float*)d_in[12];
    const float* obj_b2    = (const float*)d_in[13];
    const float* fuse_s_w1 = (const float*)d_in[14];
    const float* fuse_s_b1 = (const float*)d_in[15];
    const float* fuse_s_w2 = (const float*)d_in[16];
    const float* fuse_s_b2 = (const float*)d_in[17];
    const float* fuse_o_w1 = (const float*)d_in[18];
    const float* fuse_o_b1 = (const float*)d_in[19];
    const float* fuse_o_w2 = (const float*)d_in[20];
    const float* fuse_o_b2 = (const float*)d_in[21];
    const float* W_rs      = (const float*)d_in[22];
    const float* W_ro      = (const float*)d_in[23];
    const float* rel_w1    = (const float*)d_in[24];
    const float* rel_b1    = (const float*)d_in[25];
    const float* rel_w2    = (const float*)d_in[26];
    const float* rel_b2    = (const float*)d_in[27];
    float* out = (float*)d_out;

    __half *pX16;
    __half *pW1h_s, *pW1l_s, *pW1h_o, *pW1l_o;
    __half *pY1_s, *pY1_o, *pY2_s, *pY2_o;
    __half *pWfh_s, *pWfl_s, *pWfh_o, *pWfl_o;
    __half *pWcch_s, *pWccl_s, *pWcch_o, *pWccl_o;
    float *pA, *pB, *pWsum_s, *pWsum_o, *pWc_s, *pWc_o;
    float *pc_subj, *pc_obj, *pbf_s, *pbf_o, *pcv_s, *pcv_o;
    cudaGetSymbolAddress((void**)&pX16, g_X16);
    cudaGetSymbolAddress((void**)&pW1h_s, g_W1h_s);
    cudaGetSymbolAddress((void**)&pW1l_s, g_W1l_s);
    cudaGetSymbolAddress((void**)&pW1h_o, g_W1h_o);
    cudaGetSymbolAddress((void**)&pW1l_o, g_W1l_o);
    cudaGetSymbolAddress((void**)&pY1_s, g_Y1_s);
    cudaGetSymbolAddress((void**)&pY1_o, g_Y1_o);
    cudaGetSymbolAddress((void**)&pY2_s, g_Y2_s);
    cudaGetSymbolAddress((void**)&pY2_o, g_Y2_o);
    cudaGetSymbolAddress((void**)&pWfh_s, g_Wfh_s);
    cudaGetSymbolAddress((void**)&pWfl_s, g_Wfl_s);
    cudaGetSymbolAddress((void**)&pWfh_o, g_Wfh_o);
    cudaGetSymbolAddress((void**)&pWfl_o, g_Wfl_o);
    cudaGetSymbolAddress((void**)&pWcch_s, g_Wcch_s);
    cudaGetSymbolAddress((void**)&pWccl_s, g_Wccl_s);
    cudaGetSymbolAddress((void**)&pWcch_o, g_Wcch_o);
    cudaGetSymbolAddress((void**)&pWccl_o, g_Wccl_o);
    cudaGetSymbolAddress((void**)&pA, g_A);
    cudaGetSymbolAddress((void**)&pB, g_B);
    cudaGetSymbolAddress((void**)&pWsum_s, g_Wsum_s);
    cudaGetSymbolAddress((void**)&pWsum_o, g_Wsum_o);
    cudaGetSymbolAddress((void**)&pWc_s, g_Wc_s);
    cudaGetSymbolAddress((void**)&pWc_o, g_Wc_o);
    cudaGetSymbolAddress((void**)&pc_subj, g_c_subj);
    cudaGetSymbolAddress((void**)&pc_obj,  g_c_obj);
    cudaGetSymbolAddress((void**)&pbf_s,  g_bf_s);
    cudaGetSymbolAddress((void**)&pbf_o,  g_bf_o);
    cudaGetSymbolAddress((void**)&pcv_s,  g_cvec_s);
    cudaGetSymbolAddress((void**)&pcv_o,  g_cvec_o);

    static bool attr_set = false;
    if (!attr_set) {
        cudaFuncSetAttribute(pairwise_hmma_kernel,
                             cudaFuncAttributeMaxDynamicSharedMemorySize, PSMEM);
        cudaFuncSetAttribute(chain_hmma_kernel<true, true>,
                             cudaFuncAttributeMaxDynamicSharedMemorySize, CSMEM);
        cudaFuncSetAttribute(chain_hmma_kernel<false, false>,
                             cudaFuncAttributeMaxDynamicSharedMemorySize, CSMEM);
        attr_set = true;
    }

    // 1. pack + precompute
    pack_x_kernel<<<NROWS, 256>>>(roi, spatial);
    split_w1_kernel<<<(HH * KP1 + 255) / 256, 256>>>(subj_w1, obj_w1);
    split_w2_kernel<<<512, 256>>>(rel_w2);
    pre_vec_kernel<<<HH, 128>>>(subj_w1, subj_b1, obj_w1, obj_b1, rel_w1, rel_b1,
                                subj_emb, obj_emb, pred_emb, fuse_s_w1, fuse_o_w1);
    nn_gemm_kernel<false><<<dim3(4, 8, 2), 256>>>(
        rel_w1, W_rs, pWc_s, nullptr, nullptr,
        rel_w1, W_ro, pWc_o, nullptr, nullptr,
        DD, DD, RELIN, DD);
    nn_gemm_kernel<true><<<dim3(8, 8, 2), 256>>>(
        pWsum_s, subj_w2, nullptr, pWfh_s, pWfl_s,
        pWsum_o, obj_w2,  nullptr, pWfh_o, pWfl_o,
        HH, DD, DD, HH);
    nn_gemm_kernel<true><<<dim3(8, 8, 2), 256>>>(
        pWc_s, fuse_s_w2, nullptr, pWcch_s, pWccl_s,
        pWc_o, fuse_o_w2, nullptr, pWcch_o, pWccl_o,
        HH, DD, DD, HH);
    gemv4_kernel<<<dim3(64, 4), 256>>>(subj_b2, obj_b2, fuse_s_b1, fuse_o_b1,
                                       fuse_s_b2, fuse_o_b2);

    dim3 cgrid(HH / 128, NROWS / 128, 2);

    // 2. layer 1: relu(X @ W1^T + c) -> Y1 fp16
    chain_hmma_kernel<true, true><<<cgrid, 256, CSMEM>>>(
        pX16, pX16, KP1,
        pW1h_s, pW1l_s, pW1h_o, pW1l_o,
        pc_subj, pc_obj,
        nullptr, nullptr,
        pY1_s, pY1_o,
        HH, KP1);

    // 3. layer 2: relu(Y1 @ Wf^T + bf) -> Y2 fp16
    chain_hmma_kernel<true, true><<<cgrid, 256, CSMEM>>>(
        pY1_s, pY1_o, HH,
        pWfh_s, pWfl_s, pWfh_o, pWfl_o,
        pbf_s, pbf_o,
        nullptr, nullptr,
        pY2_s, pY2_o,
        HH, HH);

    // 4. layer 3: Y2 @ Wcc^T + cvec(+bias512 for A) -> A/B fp32
    chain_hmma_kernel<false, false><<<cgrid, 256, CSMEM>>>(
        pY2_s, pY2_o, HH,
        pWcch_s, pWccl_s, pWcch_o, pWccl_o,
        pcv_s, pcv_o,
        pA, pB,
        nullptr, nullptr,
        HH, HH);

    // 5. pairwise GEMM (HMMA fp16 2-term, pipelined)
    pairwise_hmma_kernel<<<dim3(2, 32, 64), 256, PSMEM>>>(rel_b2, out);

    (void)in_sizes; (void)n_in; (void)out_size;
}

// round 9
// speedup vs baseline: 1.8500x; 1.4724x over previous
#include <cuda_runtime.h>
#include <cuda_bf16.h>
#include <cuda_fp16.h>
#include <cstdint>
#include <cstddef>

// ---------------- problem constants ----------------
#define TT      64
#define MM      64
#define NROWS   4096      // T*M
#define ROI     2048
#define SPA     4
#define WORD    300
#define ROISPA  2052      // ROI+SPA
#define INW     2352      // ROI+SPA+WORD
#define HH      512
#define DD      256
#define RELIN   556       // D + WORD
#define KP1     2080      // ROISPA padded to 65*32

// ---------------- scratch (device globals; no allocation) ----------------
__device__ __half g_X16 [NROWS * KP1];                      // activations fp16
__device__ __half g_W1_s[HH * KP1], g_W1_o[HH * KP1];       // weights fp16 (single plane)
__device__ __half g_Y1_s[NROWS * HH], g_Y1_o[NROWS * HH];
__device__ __half g_Y2_s[NROWS * HH], g_Y2_o[NROWS * HH];
__device__ __half g_Wf_s[HH * HH], g_Wf_o[HH * HH];
__device__ __half g_Wcc_s[HH * HH], g_Wcc_o[HH * HH];
__device__ float g_A[NROWS * HH];      // A + bias512 folded in
__device__ float g_B[NROWS * HH];
__device__ float g_Wsum_s[HH * DD], g_Wsum_o[HH * DD];
__device__ float g_Wc_s  [HH * DD], g_Wc_o  [HH * DD];
__device__ float g_c_subj[HH], g_c_obj[HH], g_bias512[HH];
__device__ float g_bf_s[HH], g_bf_o[HH], g_cvec_s[HH], g_cvec_o[HH];
__device__ __half g_W2[DD * HH];

// ---------------- helpers ----------------
__device__ __forceinline__ uint32_t smem_u32(const void* p) {
    uint32_t a;
    asm("{ .reg .u64 t; cvta.to.shared.u64 t, %1; cvt.u32.u64 %0, t; }"
        : "=r"(a) : "l"(p));
    return a;
}
__device__ __forceinline__ void ldsm4(uint32_t* r, uint32_t addr) {
    asm volatile("ldmatrix.sync.aligned.m8n8.x4.shared.b16 {%0,%1,%2,%3}, [%4];"
        : "=r"(r[0]), "=r"(r[1]), "=r"(r[2]), "=r"(r[3]) : "r"(addr));
}
__device__ __forceinline__ void mma_f16(float* c, const uint32_t* a, const uint32_t* b) {
    asm volatile(
        "mma.sync.aligned.m16n8k16.row.col.f32.f16.f16.f32 "
        "{%0,%1,%2,%3}, {%4,%5,%6,%7}, {%8,%9}, {%0,%1,%2,%3};"
        : "+f"(c[0]), "+f"(c[1]), "+f"(c[2]), "+f"(c[3])
        : "r"(a[0]), "r"(a[1]), "r"(a[2]), "r"(a[3]), "r"(b[0]), "r"(b[1]));
}
__device__ __forceinline__ void cp16(uint32_t dst, const void* src) {
    asm volatile("cp.async.ca.shared.global [%0], [%1], 16;" :: "r"(dst), "l"(src));
}
__device__ __forceinline__ void cp_commit() {
    asm volatile("cp.async.commit_group;");
}
__device__ __forceinline__ void cp_wait0() {
    asm volatile("cp.async.wait_group 0;" ::: "memory");
}

// ---------------- pack X = [roi | spatial | 0pad] -> fp16 ----------------
__global__ void pack_x_kernel(const float* __restrict__ roi,
                              const float* __restrict__ spa) {
    int r = blockIdx.x;
    for (int k = threadIdx.x; k < KP1; k += blockDim.x) {
        float v = 0.f;
        if (k < ROI)         v = roi[(size_t)r * ROI + k];
        else if (k < ROISPA) v = spa[(size_t)r * SPA + (k - ROI)];
        g_X16[(size_t)r * KP1 + k] = __float2half_rn(v);
    }
}

// ---------------- convert layer-1 weights -> fp16 ----------------
__global__ void split_w1_kernel(const float* __restrict__ s_w1,
                                const float* __restrict__ o_w1) {
    int idx = blockIdx.x * 256 + threadIdx.x;
    if (idx >= HH * KP1) return;
    int n = idx / KP1, k = idx - n * KP1;
    float vs = (k < ROISPA) ? s_w1[(size_t)n * INW + k] : 0.f;
    float vo = (k < ROISPA) ? o_w1[(size_t)n * INW + k] : 0.f;
    g_W1_s[idx] = __float2half_rn(vs);
    g_W1_o[idx] = __float2half_rn(vo);
}

// ---------------- convert rel_w2 -> fp16 ----------------
__global__ void split_w2_kernel(const float* __restrict__ w2) {
    int idx = blockIdx.x * 256 + threadIdx.x;
    g_W2[idx] = __float2half_rn(w2[idx]);
}

// ---------------- constant biases + Wsum ----------------
__global__ void pre_vec_kernel(const float* __restrict__ subj_w1, const float* __restrict__ subj_b1,
                               const float* __restrict__ obj_w1,  const float* __restrict__ obj_b1,
                               const float* __restrict__ rel_w1,  const float* __restrict__ rel_b1,
                               const float* __restrict__ subj_emb, const float* __restrict__ obj_emb,
                               const float* __restrict__ pred_emb,
                               const float* __restrict__ fuse_s_w1, const float* __restrict__ fuse_o_w1) {
    int h = blockIdx.x;
    int t = threadIdx.x;
    float s1 = 0.f, s2 = 0.f, s3 = 0.f;
    for (int w = t; w < WORD; w += 128) {
        s1 += subj_w1[(size_t)h * INW + ROISPA + w] * subj_emb[w];
        s2 += obj_w1 [(size_t)h * INW + ROISPA + w] * obj_emb[w];
        s3 += rel_w1 [(size_t)h * RELIN + DD + w]   * pred_emb[w];
    }
    for (int o = 16; o > 0; o >>= 1) {
        s1 += __shfl_down_sync(0xffffffffu, s1, o);
        s2 += __shfl_down_sync(0xffffffffu, s2, o);
        s3 += __shfl_down_sync(0xffffffffu, s3, o);
    }
    __shared__ float red[3][4];
    int wrp = t >> 5, lan = t & 31;
    if (lan == 0) { red[0][wrp] = s1; red[1][wrp] = s2; red[2][wrp] = s3; }
    __syncthreads();
    if (t == 0) {
        g_c_subj[h]  = red[0][0] + red[0][1] + red[0][2] + red[0][3] + subj_b1[h];
        g_c_obj[h]   = red[1][0] + red[1][1] + red[1][2] + red[1][3] + obj_b1[h];
        g_bias512[h] = red[2][0] + red[2][1] + red[2][2] + red[2][3] + rel_b1[h];
    }
    for (int d = t; d < DD; d += 128) {
        g_Wsum_s[h * DD + d] = fuse_s_w1[(size_t)h * (2*DD) + d] + fuse_s_w1[(size_t)h * (2*DD) + DD + d];
        g_Wsum_o[h * DD + d] = fuse_o_w1[(size_t)h * (2*DD) + d] + fuse_o_w1[(size_t)h * (2*DD) + DD + d];
    }
}

// ---------------- tiled NN GEMM: C = A(MxK) @ B(KxN) ----------------
template<bool F16OUT>
__global__ __launch_bounds__(256)
void nn_gemm_kernel(const float* __restrict__ A0, const float* __restrict__ B0,
                    float* __restrict__ C0, __half* __restrict__ Ch0,
                    const float* __restrict__ A1, const float* __restrict__ B1,
                    float* __restrict__ C1, __half* __restrict__ Ch1,
                    int N, int K, int lda, int ldb) {
    __shared__ float Ask[16][68];
    __shared__ float Bs [16][68];
    const int br = blockIdx.z;
    const float* A = br ? A1 : A0;
    const float* B = br ? B1 : B0;
    const int m0 = blockIdx.y * 64, n0 = blockIdx.x * 64;
    const int tid = threadIdx.x;
    const int tr = tid >> 4, tc = tid & 15;
    float acc[4][4];
    #pragma unroll
    for (int i = 0; i < 4; i++)
        #pragma unroll
        for (int j = 0; j < 4; j++) acc[i][j] = 0.f;

    for (int k0 = 0; k0 < K; k0 += 16) {
        {
            int r = tid >> 2, kq = (tid & 3) * 4;
            float4 v = *reinterpret_cast<const float4*>(&A[(size_t)(m0 + r) * lda + k0 + kq]);
            Ask[kq + 0][r] = v.x; Ask[kq + 1][r] = v.y;
            Ask[kq + 2][r] = v.z; Ask[kq + 3][r] = v.w;
        }
        {
            int k = tid >> 4, nq = (tid & 15) * 4;
            float4 v = *reinterpret_cast<const float4*>(&B[(size_t)(k0 + k) * ldb + n0 + nq]);
            *reinterpret_cast<float4*>(&Bs[k][nq]) = v;
        }
        __syncthreads();
        #pragma unroll
        for (int k = 0; k < 16; k++) {
            float a[4], b[4];
            *reinterpret_cast<float4*>(a) = *reinterpret_cast<const float4*>(&Ask[k][tr * 4]);
            *reinterpret_cast<float4*>(b) = *reinterpret_cast<const float4*>(&Bs[k][tc * 4]);
            #pragma unroll
            for (int i = 0; i < 4; i++)
                #pragma unroll
                for (int j = 0; j < 4; j++)
                    acc[i][j] = fmaf(a[i], b[j], acc[i][j]);
        }
        __syncthreads();
    }

    if (F16OUT) {
        __half* Ch = br ? Ch1 : Ch0;
        #pragma unroll
        for (int i = 0; i < 4; i++)
            #pragma unroll
            for (int j = 0; j < 4; j++) {
                size_t off = (size_t)(m0 + tr * 4 + i) * N + n0 + tc * 4 + j;
                Ch[off] = __float2half_rn(acc[i][j]);
            }
    } else {
        float* C = br ? C1 : C0;
        #pragma unroll
        for (int i = 0; i < 4; i++)
            #pragma unroll
            for (int j = 0; j < 4; j++)
                C[(size_t)(m0 + tr * 4 + i) * N + n0 + tc * 4 + j] = acc[i][j];
    }
}

// ---------------- batched small GEMV for bias folds ----------------
__global__ void gemv4_kernel(const float* __restrict__ subj_b2, const float* __restrict__ obj_b2,
                             const float* __restrict__ fuse_s_b1, const float* __restrict__ fuse_o_b1,
                             const float* __restrict__ fuse_s_b2, const float* __restrict__ fuse_o_b2) {
    int which = blockIdx.y;
    const float *A, *v, *add; float* o;
    if      (which == 0) { A = g_Wsum_s; v = subj_b2;  add = fuse_s_b1; o = g_bf_s; }
    else if (which == 1) { A = g_Wsum_o; v = obj_b2;   add = fuse_o_b1; o = g_bf_o; }
    else if (which == 2) { A = g_Wc_s;   v = fuse_s_b2; add = g_bias512; o = g_cvec_s; }
    else                 { A = g_Wc_o;   v = fuse_o_b2; add = nullptr;  o = g_cvec_o; }
    int h = blockIdx.x * 8 + (threadIdx.x >> 5);
    int lane = threadIdx.x & 31;
    float s = 0.f;
    for (int d = lane; d < DD; d += 32) s += A[h * DD + d] * v[d];
    #pragma unroll
    for (int off = 16; off > 0; off >>= 1) s += __shfl_down_sync(0xffffffffu, s, off);
    if (lane == 0) o[h] = s + (add ? add[h] : 0.f);
}

// ================= chain HMMA GEMM (fp16, cp.async double-buffered) ====
// planes per buffer: X (10240) | W (10240)
#define CPSTR   80
#define CBUFSZ  20480
#define CSMEM   (512 + 2 * CBUFSZ)   // 41472

template<bool RELU, bool F16OUT>
__global__ __launch_bounds__(256, 2)
void chain_hmma_kernel(const __half* __restrict__ X0, const __half* __restrict__ X1,
                       int ldx,
                       const __half* __restrict__ W0, const __half* __restrict__ W1,
                       const float* __restrict__ bias0, const float* __restrict__ bias1,
                       float* __restrict__ C0, float* __restrict__ C1,
                       __half* __restrict__ Co0, __half* __restrict__ Co1,
                       int N, int K) {
    extern __shared__ char smem[];
    const uint32_t su = smem_u32(smem);
    float* biasS = reinterpret_cast<float*>(smem);

    const int tid  = threadIdx.x;
    const int wid  = tid >> 5;
    const int lane = tid & 31;
    const int wm   = wid >> 1;
    const int wn   = wid & 1;
    const int n0   = blockIdx.x * 128;
    const int m0   = blockIdx.y * 128;
    const int br   = blockIdx.z;

    const __half* X = br ? X1 : X0;
    const __half* W = br ? W1 : W0;
    const float* bias = br ? bias1 : bias0;

    if (tid < 128) biasS[tid] = bias[n0 + tid];

    auto stage = [&](int k0, int b) {
        uint32_t base = su + 512 + (uint32_t)b * CBUFSZ;
        #pragma unroll
        for (int e = 0; e < 2; e++) {
            int idx = e * 256 + tid;
            int r = idx >> 2, q = idx & 3;
            cp16(base +         r * CPSTR + q * 16, X + (size_t)(m0 + r) * ldx + k0 + q * 8);
            cp16(base + 10240 + r * CPSTR + q * 16, W + (size_t)(n0 + r) * K + k0 + q * 8);
        }
    };

    const uint32_t h_off = (uint32_t)((lane & 15) * CPSTR + (lane >> 4) * 16);
    const uint32_t w_off = (uint32_t)(((lane & 7) + ((lane >> 4) << 3)) * CPSTR
                                      + ((lane >> 3) & 1) * 16);

    float acc[2][8][4];
    #pragma unroll
    for (int mb = 0; mb < 2; mb++)
        #pragma unroll
        for (int nb = 0; nb < 8; nb++)
            #pragma unroll
            for (int q = 0; q < 4; q++) acc[mb][nb][q] = 0.f;

    stage(0, 0); cp_commit();
    const int nk = K / 32;

    for (int c = 0; c < nk; c++) {
        cp_wait0();
        __syncthreads();
        if (c + 1 < nk) { stage((c + 1) * 32, (c + 1) & 1); cp_commit(); }

        const uint32_t base = su + 512 + (uint32_t)(c & 1) * CBUFSZ;
        #pragma unroll
        for (int ks = 0; ks < 2; ks++) {
            uint32_t a[2][4];
            const uint32_t hbase = base + wm * (32 * CPSTR) + ks * 32 + h_off;
            ldsm4(a[0], hbase);
            ldsm4(a[1], hbase + 16 * CPSTR);
            const uint32_t wbase = base + 10240 + wn * (64 * CPSTR) + ks * 32 + w_off;
            #pragma unroll
            for (int g = 0; g < 4; g++) {
                uint32_t b[4];
                ldsm4(b, wbase + g * (16 * CPSTR));
                mma_f16(acc[0][g * 2 + 0], a[0], b);
                mma_f16(acc[0][g * 2 + 1], a[0], b + 2);
                mma_f16(acc[1][g * 2 + 0], a[1], b);
                mma_f16(acc[1][g * 2 + 1], a[1], b + 2);
            }
        }
    }

    // ---- epilogue ----
    const int qr = lane >> 2, qc = (lane & 3) * 2;
    float* C = br ? C1 : C0;
    __half* Co = br ? Co1 : Co0;
    #pragma unroll
    for (int mb = 0; mb < 2; mb++) {
        int rA = m0 + wm * 32 + mb * 16 + qr;
        int rB = rA + 8;
        #pragma unroll
        for (int nb = 0; nb < 8; nb++) {
            int ln = qc + wn * 64 + nb * 8;
            int col = n0 + ln;
            float vA0 = acc[mb][nb][0] + biasS[ln];
            float vA1 = acc[mb][nb][1] + biasS[ln + 1];
            float vB0 = acc[mb][nb][2] + biasS[ln];
            float vB1 = acc[mb][nb][3] + biasS[ln + 1];
            if (RELU) {
                vA0 = fmaxf(vA0, 0.f); vA1 = fmaxf(vA1, 0.f);
                vB0 = fmaxf(vB0, 0.f); vB1 = fmaxf(vB1, 0.f);
            }
            if (F16OUT) {
                *reinterpret_cast<__half2*>(&Co[(size_t)rA * N + col]) = __floats2half2_rn(vA0, vA1);
                *reinterpret_cast<__half2*>(&Co[(size_t)rB * N + col]) = __floats2half2_rn(vB0, vB1);
            } else {
                *reinterpret_cast<float2*>(&C[(size_t)rA * N + col]) = make_float2(vA0, vA1);
                *reinterpret_cast<float2*>(&C[(size_t)rB * N + col]) = make_float2(vB0, vB1);
            }
        }
    }
}

// ================= HMMA pairwise kernel (fp16, cp.async pipelined) ======
// smem layout:
//  0      b2        512
//  512    H (fp16)  10240
//  10752  buf0 { A 2x128B=256 | B 64x144=9216 | W 10240 } = 19712
//  30464  buf1
#define PW_H     512
#define PW_BUF0  10752
#define PW_BUFSZ 19712
#define PSTR     80
#define PSMEM    (PW_BUF0 + 2 * PW_BUFSZ)   // 50176

__global__ __launch_bounds__(256, 2)
void pairwise_hmma_kernel(const float* __restrict__ b2v,
                          float* __restrict__ out) {
    extern __shared__ char smem[];
    const uint32_t su = smem_u32(smem);
    float* bs2 = reinterpret_cast<float*>(smem);

    const int tid  = threadIdx.x;
    const int wid  = tid >> 5;
    const int lane = tid & 31;
    const int wm   = wid >> 1;
    const int wn   = wid & 1;

    const int n0  = blockIdx.x * 128;
    const int ib2 = blockIdx.y * 2;
    const int t   = blockIdx.z;

    if (tid < 128) bs2[tid] = b2v[n0 + tid];

    const size_t arow0 = (size_t)(t * 64 + ib2) * HH;
    const size_t brow0 = (size_t)(t * 64) * HH;

    auto stage = [&](int k0, int b) {
        uint32_t base = su + PW_BUF0 + (uint32_t)b * PW_BUFSZ;
        if (tid < 16) {                            // A (bias pre-folded): 2 rows x 32 f
            int r = tid >> 3, q = tid & 7;
            cp16(base + r * 128 + q * 16, g_A + arow0 + (size_t)r * HH + k0 + q * 4);
        }
        #pragma unroll
        for (int e = 0; e < 2; e++) {              // B: 64 x 32 f, stride 144B
            int idx = e * 256 + tid;
            int j = idx >> 3, q = idx & 7;
            cp16(base + 256 + j * 144 + q * 16, g_B + brow0 + (size_t)j * HH + k0 + q * 4);
        }
        #pragma unroll
        for (int e = 0; e < 2; e++) {              // W: 128 x 32 fp16
            int idx = e * 256 + tid;
            int n = idx >> 2, q = idx & 3;
            cp16(base + 9472 + n * PSTR + q * 16, g_W2 + (size_t)(n0 + n) * HH + k0 + q * 8);
        }
    };

    const uint32_t h_off = (uint32_t)((lane & 15) * PSTR + (lane >> 4) * 16);
    const uint32_t w_off = (uint32_t)(((lane & 7) + ((lane >> 4) << 3)) * PSTR
                                      + ((lane >> 3) & 1) * 16);

    float acc[2][8][4];
    #pragma unroll
    for (int mb = 0; mb < 2; mb++)
        #pragma unroll
        for (int nb = 0; nb < 8; nb++)
            #pragma unroll
            for (int q = 0; q < 4; q++) acc[mb][nb][q] = 0.f;

    stage(0, 0); cp_commit();

    for (int c = 0; c < 16; c++) {
        cp_wait0();
        __syncthreads();                 // buf(c) ready; all mma(c-1) reads done
        if (c + 1 < 16) { stage((c + 1) * 32, (c + 1) & 1); cp_commit(); }

        const uint32_t bo = PW_BUF0 + (uint32_t)(c & 1) * PW_BUFSZ;
        const float* AsB = reinterpret_cast<const float*>(smem + bo);
        const float* BsB = reinterpret_cast<const float*>(smem + bo + 256);

        // ---- build H (128 x 32 fp16), bias pre-folded into A ----
        #pragma unroll
        for (int e = 0; e < 8; e++) {
            int idx = e * 256 + tid;
            int p  = idx >> 4;
            int kp = idx & 15;
            int k  = kp * 2;
            int i  = p >> 6, j = p & 63;
            float2 av = *reinterpret_cast<const float2*>(&AsB[i * 32 + k]);
            float2 bv = *reinterpret_cast<const float2*>(&BsB[j * 36 + k]);
            float v0 = fmaxf(av.x - bv.x, 0.f);
            float v1 = fmaxf(av.y - bv.y, 0.f);
            *reinterpret_cast<__half2*>(smem + PW_H + p * PSTR + k * 2) =
                __floats2half2_rn(v0, v1);
        }
        __syncthreads();                 // H staged

        const uint32_t base = su + bo;
        #pragma unroll
        for (int ks = 0; ks < 2; ks++) {
            uint32_t a[2][4];
            const uint32_t hbase = su + PW_H + wm * (32 * PSTR) + ks * 32 + h_off;
            ldsm4(a[0], hbase);
            ldsm4(a[1], hbase + 16 * PSTR);
            const uint32_t wbase = base + 9472 + wn * (64 * PSTR) + ks * 32 + w_off;
            #pragma unroll
            for (int g = 0; g < 4; g++) {
                uint32_t b[4];
                ldsm4(b, wbase + g * (16 * PSTR));
                mma_f16(acc[0][g * 2 + 0], a[0], b);
                mma_f16(acc[0][g * 2 + 1], a[0], b + 2);
                mma_f16(acc[1][g * 2 + 0], a[1], b);
                mma_f16(acc[1][g * 2 + 1], a[1], b + 2);
            }
        }
    }

    const int qr = lane >> 2, qc = (lane & 3) * 2;
    #pragma unroll
    for (int mb = 0; mb < 2; mb++) {
        int rA = wm * 32 + mb * 16 + qr;
        int rB = rA + 8;
        float* oA = out + ((size_t)(t * 64 + ib2 + (rA >> 6)) * 64 + (rA & 63)) * 256
                        + n0 + wn * 64 + qc;
        float* oB = out + ((size_t)(t * 64 + ib2 + (rB >> 6)) * 64 + (rB & 63)) * 256
                        + n0 + wn * 64 + qc;
        #pragma unroll
        for (int nb = 0; nb < 8; nb++) {
            int ln = wn * 64 + nb * 8 + qc;
            float2 vA = make_float2(acc[mb][nb][0] + bs2[ln],
                                    acc[mb][nb][1] + bs2[ln + 1]);
            float2 vB = make_float2(acc[mb][nb][2] + bs2[ln],
                                    acc[mb][nb][3] + bs2[ln + 1]);
            *reinterpret_cast<float2*>(oA + nb * 8) = vA;
            *reinterpret_cast<float2*>(oB + nb * 8) = vB;
        }
    }
}

// ---------------- host launch ----------------
extern "C" void kernel_launch(void* const* d_in, const int* in_sizes, int n_in,
                              void* d_out, int out_size) {
    const float* roi       = (const float*)d_in[0];
    const float* spatial   = (const float*)d_in[1];
    const float* subj_emb  = (const float*)d_in[3];
    const float* obj_emb   = (const float*)d_in[4];
    const float* pred_emb  = (const float*)d_in[5];
    const float* subj_w1   = (const float*)d_in[6];
    const float* subj_b1   = (const float*)d_in[7];
    const float* subj_w2   = (const float*)d_in[8];
    const float* subj_b2   = (const float*)d_in[9];
    const float* obj_w1    = (const float*)d_in[10];
    const float* obj_b1    = (const float*)d_in[11];
    const float* obj_w2    = (const float*)d_in[12];
    const float* obj_b2    = (const float*)d_in[13];
    const float* fuse_s_w1 = (const float*)d_in[14];
    const float* fuse_s_b1 = (const float*)d_in[15];
    const float* fuse_s_w2 = (const float*)d_in[16];
    const float* fuse_s_b2 = (const float*)d_in[17];
    const float* fuse_o_w1 = (const float*)d_in[18];
    const float* fuse_o_b1 = (const float*)d_in[19];
    const float* fuse_o_w2 = (const float*)d_in[20];
    const float* fuse_o_b2 = (const float*)d_in[21];
    const float* W_rs      = (const float*)d_in[22];
    const float* W_ro      = (const float*)d_in[23];
    const float* rel_w1    = (const float*)d_in[24];
    const float* rel_b1    = (const float*)d_in[25];
    const float* rel_w2    = (const float*)d_in[26];
    const float* rel_b2    = (const float*)d_in[27];
    float* out = (float*)d_out;

    __half *pX16, *pW1_s, *pW1_o;
    __half *pY1_s, *pY1_o, *pY2_s, *pY2_o;
    __half *pWf_s, *pWf_o, *pWcc_s, *pWcc_o;
    float *pA, *pB, *pWsum_s, *pWsum_o, *pWc_s, *pWc_o;
    float *pc_subj, *pc_obj, *pbf_s, *pbf_o, *pcv_s, *pcv_o;
    cudaGetSymbolAddress((void**)&pX16, g_X16);
    cudaGetSymbolAddress((void**)&pW1_s, g_W1_s);
    cudaGetSymbolAddress((void**)&pW1_o, g_W1_o);
    cudaGetSymbolAddress((void**)&pY1_s, g_Y1_s);
    cudaGetSymbolAddress((void**)&pY1_o, g_Y1_o);
    cudaGetSymbolAddress((void**)&pY2_s, g_Y2_s);
    cudaGetSymbolAddress((void**)&pY2_o, g_Y2_o);
    cudaGetSymbolAddress((void**)&pWf_s, g_Wf_s);
    cudaGetSymbolAddress((void**)&pWf_o, g_Wf_o);
    cudaGetSymbolAddress((void**)&pWcc_s, g_Wcc_s);
    cudaGetSymbolAddress((void**)&pWcc_o, g_Wcc_o);
    cudaGetSymbolAddress((void**)&pA, g_A);
    cudaGetSymbolAddress((void**)&pB, g_B);
    cudaGetSymbolAddress((void**)&pWsum_s, g_Wsum_s);
    cudaGetSymbolAddress((void**)&pWsum_o, g_Wsum_o);
    cudaGetSymbolAddress((void**)&pWc_s, g_Wc_s);
    cudaGetSymbolAddress((void**)&pWc_o, g_Wc_o);
    cudaGetSymbolAddress((void**)&pc_subj, g_c_subj);
    cudaGetSymbolAddress((void**)&pc_obj,  g_c_obj);
    cudaGetSymbolAddress((void**)&pbf_s,  g_bf_s);
    cudaGetSymbolAddress((void**)&pbf_o,  g_bf_o);
    cudaGetSymbolAddress((void**)&pcv_s,  g_cvec_s);
    cudaGetSymbolAddress((void**)&pcv_o,  g_cvec_o);

    static bool attr_set = false;
    if (!attr_set) {
        cudaFuncSetAttribute(pairwise_hmma_kernel,
                             cudaFuncAttributeMaxDynamicSharedMemorySize, PSMEM);
        cudaFuncSetAttribute(chain_hmma_kernel<true, true>,
                             cudaFuncAttributeMaxDynamicSharedMemorySize, CSMEM);
        cudaFuncSetAttribute(chain_hmma_kernel<false, false>,
                             cudaFuncAttributeMaxDynamicSharedMemorySize, CSMEM);
        attr_set = true;
    }

    // 1. pack + precompute
    pack_x_kernel<<<NROWS, 256>>>(roi, spatial);
    split_w1_kernel<<<(HH * KP1 + 255) / 256, 256>>>(subj_w1, obj_w1);
    split_w2_kernel<<<512, 256>>>(rel_w2);
    pre_vec_kernel<<<HH, 128>>>(subj_w1, subj_b1, obj_w1, obj_b1, rel_w1, rel_b1,
                                subj_emb, obj_emb, pred_emb, fuse_s_w1, fuse_o_w1);
    nn_gemm_kernel<false><<<dim3(4, 8, 2), 256>>>(
        rel_w1, W_rs, pWc_s, nullptr,
        rel_w1, W_ro, pWc_o, nullptr,
        DD, DD, RELIN, DD);
    nn_gemm_kernel<true><<<dim3(8, 8, 2), 256>>>(
        pWsum_s, subj_w2, nullptr, pWf_s,
        pWsum_o, obj_w2,  nullptr, pWf_o,
        HH, DD, DD, HH);
    nn_gemm_kernel<true><<<dim3(8, 8, 2), 256>>>(
        pWc_s, fuse_s_w2, nullptr, pWcc_s,
        pWc_o, fuse_o_w2, nullptr, pWcc_o,
        HH, DD, DD, HH);
    gemv4_kernel<<<dim3(64, 4), 256>>>(subj_b2, obj_b2, fuse_s_b1, fuse_o_b1,
                                       fuse_s_b2, fuse_o_b2);

    dim3 cgrid(HH / 128, NROWS / 128, 2);

    // 2. layer 1: relu(X @ W1^T + c) -> Y1 fp16
    chain_hmma_kernel<true, true><<<cgrid, 256, CSMEM>>>(
        pX16, pX16, KP1,
        pW1_s, pW1_o,
        pc_subj, pc_obj,
        nullptr, nullptr,
        pY1_s, pY1_o,
        HH, KP1);

    // 3. layer 2: relu(Y1 @ Wf^T + bf) -> Y2 fp16
    chain_hmma_kernel<true, true><<<cgrid, 256, CSMEM>>>(
        pY1_s, pY1_o, HH,
        pWf_s, pWf_o,
        pbf_s, pbf_o,
        nullptr, nullptr,
        pY2_s, pY2_o,
        HH, HH);

    // 4. layer 3: Y2 @ Wcc^T + cvec(+bias512 for A) -> A/B fp32
    chain_hmma_kernel<false, false><<<cgrid, 256, CSMEM>>>(
        pY2_s, pY2_o, HH,
        pWcc_s, pWcc_o,
        pcv_s, pcv_o,
        pA, pB,
        nullptr, nullptr,
        HH, HH);

    // 5. pairwise GEMM (HMMA fp16, pipelined)
    pairwise_hmma_kernel<<<dim3(2, 32, 64), 256, PSMEM>>>(rel_b2, out);

    (void)in_sizes; (void)n_in; (void)out_size;
}